// round 3
// baseline (speedup 1.0000x reference)
#include <cuda_runtime.h>

#define N_NODES 100000
#define N_EDGES 1600000
#define NF 64
#define NH 16

// scratch (no allocs allowed) — 16B-aligned for float4 / red.v4 access
__device__ __align__(16) float g_xl[N_NODES * NH];     // x @ Wl1
__device__ __align__(16) float g_xr[N_NODES * NH];     // x @ Wr1
__device__ __align__(16) float g_agg1[N_NODES * NH];   // segment_sum of xl[src]
__device__ __align__(16) float g_hl[N_NODES];          // h @ Wl2 (scalar per node)
__device__ __align__(16) int2  g_rec[N_EDGES];         // compacted (src, dst-or-neg)

__device__ __forceinline__ void red4(float* addr, float4 v) {
    asm volatile("red.global.add.v4.f32 [%0], {%1,%2,%3,%4};"
                 :: "l"(addr), "f"(v.x), "f"(v.y), "f"(v.z), "f"(v.w) : "memory");
}
__device__ __forceinline__ void red1(float* addr, float v) {
    asm volatile("red.global.add.f32 [%0], %1;" :: "l"(addr), "f"(v) : "memory");
}

// ---------------------------------------------------------------------------
// Kernel A: xl = x @ Wl1, xr = x @ Wr1  (combined [64,32] weight tile in smem)
// Also zeroes g_agg1 (3125 blocks * 256 threads * 2 floats = exactly N*16).
// ---------------------------------------------------------------------------
__global__ __launch_bounds__(256) void k_proj(const float* __restrict__ x,
                                              const float* __restrict__ Wl1,
                                              const float* __restrict__ Wr1) {
    __shared__ float sW[64][32];
    __shared__ float sx[32][64];
    int tid = threadIdx.x;

    for (int i = tid; i < 64 * 16; i += 256) {
        int k = i >> 4, j = i & 15;
        sW[k][j]      = Wl1[i];
        sW[k][j + 16] = Wr1[i];
    }
    int nodeBase = blockIdx.x * 32;
    const float4* x4 = (const float4*)(x + (size_t)nodeBase * NF);
    #pragma unroll
    for (int i = tid; i < 512; i += 256) {
        float4 v = x4[i];
        int row = i >> 4;
        int c = (i & 15) * 4;
        sx[row][c] = v.x; sx[row][c+1] = v.y; sx[row][c+2] = v.z; sx[row][c+3] = v.w;
    }
    __syncthreads();

    int j  = tid & 31;   // output column 0..31
    int nl = tid >> 5;   // local node group 0..7
    float a0 = 0.f, a1 = 0.f, a2 = 0.f, a3 = 0.f;
    #pragma unroll
    for (int k = 0; k < 64; k++) {
        float w = sW[k][j];
        a0 = fmaf(sx[nl     ][k], w, a0);
        a1 = fmaf(sx[nl +  8][k], w, a1);
        a2 = fmaf(sx[nl + 16][k], w, a2);
        a3 = fmaf(sx[nl + 24][k], w, a3);
    }
    float acc[4] = {a0, a1, a2, a3};
    #pragma unroll
    for (int i = 0; i < 4; i++) {
        int node = nodeBase + nl + i * 8;
        if (j < 16) g_xl[node * NH + j]        = acc[i];
        else        g_xr[node * NH + (j - 16)] = acc[i];
    }
    size_t gt = (size_t)blockIdx.x * 256 + tid;
    ((float2*)g_agg1)[gt] = make_float2(0.f, 0.f);
}

// ---------------------------------------------------------------------------
// Kernel B: edge pass 1 — mask, gather xl[src] (16 floats), vector-RED into
// agg1[dst]; emit compacted edge record for pass 2.
// edge_index is INT32 (jax default x64-disabled downcasts int64 -> int32).
// ---------------------------------------------------------------------------
__global__ __launch_bounds__(256) void k_edge1(const int* __restrict__ ei,
                                               const float* __restrict__ As,
                                               const float* __restrict__ ws) {
    int e = blockIdx.x * 256 + threadIdx.x;
    if (e >= N_EDGES) return;
    float ewm = ws[0] * As[e] + ws[1] * As[N_EDGES + e];
    int s = ei[e];
    int d = ei[N_EDGES + e];
    bool keep = (ewm != 0.0f) & ((unsigned)s < N_NODES) & ((unsigned)d < N_NODES);
    g_rec[e] = make_int2(s, keep ? d : -1);
    if (keep) {
        const float4* xs = (const float4*)g_xl + (size_t)s * 4;
        float4 v0 = xs[0], v1 = xs[1], v2 = xs[2], v3 = xs[3];
        float* base = g_agg1 + (size_t)d * NH;
        red4(base,      v0);
        red4(base + 4,  v1);
        red4(base + 8,  v2);
        red4(base + 12, v3);
    }
}

// ---------------------------------------------------------------------------
// Kernel C: per-node — h = relu(agg1 + xr + bl1); hl = h.Wl2; hr = h.Wr2;
// out[n] = hr + bl2 (initializes poisoned d_out), g_hl[n] = hl for pass 2.
// ---------------------------------------------------------------------------
__global__ __launch_bounds__(256) void k_node(const float* __restrict__ bl1,
                                              const float* __restrict__ Wl2,
                                              const float* __restrict__ bl2,
                                              const float* __restrict__ Wr2,
                                              float* __restrict__ out) {
    int n = blockIdx.x * 256 + threadIdx.x;
    if (n >= N_NODES) return;
    const float4* a4 = (const float4*)g_agg1 + (size_t)n * 4;
    const float4* r4 = (const float4*)g_xr   + (size_t)n * 4;
    float hl = 0.f, hr = 0.f;
    #pragma unroll
    for (int q = 0; q < 4; q++) {
        float4 a = a4[q];
        float4 r = r4[q];
        float h0 = fmaxf(a.x + r.x + bl1[q * 4 + 0], 0.f);
        float h1 = fmaxf(a.y + r.y + bl1[q * 4 + 1], 0.f);
        float h2 = fmaxf(a.z + r.z + bl1[q * 4 + 2], 0.f);
        float h3 = fmaxf(a.w + r.w + bl1[q * 4 + 3], 0.f);
        hl = fmaf(h0, Wl2[q * 4 + 0], hl);
        hl = fmaf(h1, Wl2[q * 4 + 1], hl);
        hl = fmaf(h2, Wl2[q * 4 + 2], hl);
        hl = fmaf(h3, Wl2[q * 4 + 3], hl);
        hr = fmaf(h0, Wr2[q * 4 + 0], hr);
        hr = fmaf(h1, Wr2[q * 4 + 1], hr);
        hr = fmaf(h2, Wr2[q * 4 + 2], hr);
        hr = fmaf(h3, Wr2[q * 4 + 3], hr);
    }
    g_hl[n] = hl;
    out[n] = hr + bl2[0];
}

// ---------------------------------------------------------------------------
// Kernel D: edge pass 2 — scalar RED of hl[src] into out[dst].
// ---------------------------------------------------------------------------
__global__ __launch_bounds__(256) void k_edge2(float* __restrict__ out) {
    int e = blockIdx.x * 256 + threadIdx.x;
    if (e >= N_EDGES) return;
    int2 r = g_rec[e];
    if (r.y >= 0) {
        red1(out + r.y, g_hl[r.x]);
    }
}

extern "C" void kernel_launch(void* const* d_in, const int* in_sizes, int n_in,
                              void* d_out, int out_size) {
    const float* x   = (const float*)d_in[0];
    const int*   ei  = (const int*)d_in[1];     // int32 (jax x64 disabled)
    const float* As  = (const float*)d_in[2];
    const float* ws  = (const float*)d_in[3];
    const float* Wl1 = (const float*)d_in[4];
    const float* bl1 = (const float*)d_in[5];
    const float* Wr1 = (const float*)d_in[6];
    const float* Wl2 = (const float*)d_in[7];
    const float* bl2 = (const float*)d_in[8];
    const float* Wr2 = (const float*)d_in[9];
    float* out = (float*)d_out;

    k_proj <<<N_NODES / 32,          256>>>(x, Wl1, Wr1);
    k_edge1<<<(N_EDGES + 255) / 256, 256>>>(ei, As, ws);
    k_node <<<(N_NODES + 255) / 256, 256>>>(bl1, Wl2, bl2, Wr2, out);
    k_edge2<<<(N_EDGES + 255) / 256, 256>>>(out);
}